// round 11
// baseline (speedup 1.0000x reference)
#include <cuda_runtime.h>

// NeRF fused render: near/far -> coarse bins -> scatter inverse-CDF sampling ->
// contraction -> alpha compositing.
// One warp per ray. Blocked sample ownership (lane owns samples 4l..4l+3).
// Compositing via exp-difference (one additive warp scan). CDF intervals
// pair-owned per lane. rcp.approx divisions.
// L2 prefetch of sigma/rgb at entry to hide DRAM latency behind CDF work.
// NOTE: redux.sync is INT-ONLY on sm_103a — float reductions use shuffles.

constexpr int T0 = 64;     // coarse intervals
constexpr int TF = 128;    // fine samples
constexpr int OUTW = 4 + 3 * TF;     // 388 floats per ray
constexpr int WPB = 8;               // warps per block
constexpr unsigned FULL = 0xffffffffu;

__device__ __forceinline__ float frcp(float x) {
    float r;
    asm("rcp.approx.f32 %0, %1;" : "=f"(r) : "f"(x));
    return r;
}

__device__ __forceinline__ void contract_pt(float zm,
                                            float ox, float oy, float oz,
                                            float dx, float dy, float dz,
                                            float& cx, float& cy, float& cz)
{
    float x = fmaf(dx, zm, ox);
    float y = fmaf(dy, zm, oy);
    float z = fmaf(dz, zm, oz);
    const float ax = fabsf(x), ay = fabsf(y), az = fabsf(z);
    const float mag = fmaxf(ax, fmaxf(ay, az));
    cx = x; cy = y; cz = z;
    if (mag >= 1.0f) {
        const float im = frcp(mag);
        const float sm = (2.0f - im) * im;
        cx = x * im; cy = y * im; cz = z * im;
        if (ax == mag)      cx = x * sm;   // argmax tie-break order x,y,z
        else if (ay == mag) cy = y * sm;
        else                cz = z * sm;
    }
}

__global__ __launch_bounds__(WPB * 32, 8)
void nerf_render_kernel(const float* __restrict__ rays_o,
                        const float* __restrict__ rays_d,
                        const float* __restrict__ aabb,
                        const float* __restrict__ wc,     // [N, 64]
                        const float* __restrict__ sigmas, // [N, 128]
                        const float* __restrict__ rgbs,   // [N, 128, 3]
                        float* __restrict__ out,          // [N, 388]
                        int N)
{
    __shared__ __align__(16) float s_zed[WPB][TF + 8];   // 129 fine edges (+pad)

    const int warp = threadIdx.x >> 5;
    const int lane = threadIdx.x & 31;
    const int ray  = blockIdx.x * WPB + warp;
    if (ray >= N) return;

    // ---- early L2 prefetch: sigma + rgb, consumed ~1000+ cycles later ----
    const float* sgp = sigmas + (size_t)ray * TF + 4 * lane;
    const float4* rg4 = reinterpret_cast<const float4*>(
        rgbs + (size_t)ray * TF * 3) + 3 * lane;
    asm volatile("prefetch.global.L2 [%0];" :: "l"(sgp));
    asm volatile("prefetch.global.L2 [%0];" :: "l"(rg4));
    asm volatile("prefetch.global.L2 [%0];" :: "l"(rg4 + 1));
    asm volatile("prefetch.global.L2 [%0];" :: "l"(rg4 + 2));

    // ---- ray + aabb ----
    const float ox = rays_o[3 * ray + 0];
    const float oy = rays_o[3 * ray + 1];
    const float oz = rays_o[3 * ray + 2];
    const float dx = rays_d[3 * ray + 0];
    const float dy = rays_d[3 * ray + 1];
    const float dz = rays_d[3 * ray + 2];

    const float ix = frcp(dx + 1e-15f);
    const float iy = frcp(dy + 1e-15f);
    const float iz = frcp(dz + 1e-15f);
    const float t0x = (aabb[0] - ox) * ix, t1x = (aabb[3] - ox) * ix;
    const float t0y = (aabb[1] - oy) * iy, t1y = (aabb[4] - oy) * iy;
    const float t0z = (aabb[2] - oz) * iz, t1z = (aabb[5] - oz) * iz;

    float nearv = fmaxf(fmaxf(fminf(t0x, t1x), fminf(t0y, t1y)), fminf(t0z, t1z));
    float farv  = fminf(fminf(fmaxf(t0x, t1x), fmaxf(t0y, t1y)), fmaxf(t0z, t1z));
    if (farv < nearv) { nearv = 1e9f; farv = 1e9f; }
    nearv = fmaxf(nearv, 0.05f);
    const float span = farv - nearv;
    const float db = span * (1.0f / 64.0f);   // coarse bin width (constant)

    // ---- CDF: lane owns weights {2l, 2l+1} -> intervals 2l, 2l+1 local ----
    const float2 wpair = *reinterpret_cast<const float2*>(
        wc + (size_t)ray * T0 + 2 * lane);
    const float wa = wpair.x + 0.01f;
    const float wb = wpair.y + 0.01f;
    const float pair = wa + wb;

    float incl = pair;
    #pragma unroll
    for (int o = 1; o < 32; o <<= 1) {
        float v = __shfl_up_sync(FULL, incl, o);
        if (lane >= o) incl += v;
    }
    float excl = __shfl_up_sync(FULL, incl, 1);
    if (lane == 0) excl = 0.0f;
    const float inv_tot = frcp(__shfl_sync(FULL, incl, 31));

    const float c_base = fminf(excl * inv_tot, 1.0f);          // C[2l]
    const float c_mid  = fminf((excl + wa) * inv_tot, 1.0f);   // C[2l+1]
    const float c_end  = fminf(incl * inv_tot, 1.0f);          // C[2l+2]

    float* zed = s_zed[warp];

    // ---- scatter fine edges: interval k covers u in [C[k], C[k+1]) ----
    #pragma unroll
    for (int h = 0; h < 2; ++h) {
        const int k = 2 * lane + h;
        const float c0 = (h == 0) ? c_base : c_mid;
        const float c1 = (h == 0) ? c_mid : c_end;

        int j0 = (int)ceilf(fmaf(129.0f, c0, -0.5f));
        int j1 = (k == 63) ? 129 : (int)ceilf(fmaf(129.0f, c1, -0.5f));
        j0 = max(j0, 0);
        j1 = min(j1, 129);

        const float inv_den = frcp(fmaxf(c1 - c0, 1e-12f));
        const float b0 = fmaf(db, (float)k, nearv);

        for (int j = j0; j < j1; ++j) {
            const float u = (j + 0.5f) * (1.0f / 129.0f);
            float t = fminf(fmaxf((u - c0) * inv_den, 0.0f), 1.0f);
            zed[j] = fmaf(t, db, b0);
        }
    }
    __syncwarp();

    // ---- blocked compositing: lane owns samples 4l..4l+3 ----
    const float4 z4 = *reinterpret_cast<const float4*>(&zed[4 * lane]);
    const float ztop = zed[TF];                         // zed[128], broadcast
    const float znxt = __shfl_down_sync(FULL, z4.x, 1); // next lane's first edge
    const float e4 = (lane == 31) ? ztop : znxt;

    const float4 sg4 = *reinterpret_cast<const float4*>(sgp);

    const float q0 = sg4.x * (z4.y - z4.x);
    const float q1 = sg4.y * (z4.z - z4.y);
    const float q2 = sg4.z * (z4.w - z4.z);
    const float q3 = sg4.w * (e4   - z4.w);

    const float p1 = q0;
    const float p2 = q0 + q1;
    const float p3 = p2 + q2;
    const float Tl = p3 + q3;               // lane-local optical depth

    // single additive warp scan over lane totals
    float iS = Tl;
    #pragma unroll
    for (int o = 1; o < 32; o <<= 1) {
        float v = __shfl_up_sync(FULL, iS, o);
        if (lane >= o) iS += v;
    }
    float S0 = __shfl_up_sync(FULL, iS, 1);
    if (lane == 0) S0 = 0.0f;

    const float E0 = __expf(-S0);
    const float E1 = __expf(-(S0 + p1));
    const float E2 = __expf(-(S0 + p2));
    const float E3 = __expf(-(S0 + p3));
    const float E4 = __expf(-(S0 + Tl));

    const float w0 = E0 - E1;
    const float w1 = E1 - E2;
    const float w2 = E2 - E3;
    const float w3 = E3 - E4;

    const float zm0 = 0.5f * (z4.x + z4.y);
    const float zm1 = 0.5f * (z4.y + z4.z);
    const float zm2 = 0.5f * (z4.z + z4.w);
    const float zm3 = 0.5f * (z4.w + e4);

    float dep = w0 * zm0 + w1 * zm1 + w2 * zm2 + w3 * zm3;

    // ---- rgb: 3x LDG.128 (L2-warm), compile-time channel mapping ----
    const float4 f0 = rg4[0];
    const float4 f1 = rg4[1];
    const float4 f2 = rg4[2];

    float img0 = w0 * f0.x + w1 * f0.w + w2 * f1.z + w3 * f2.y;
    float img1 = w0 * f0.y + w1 * f1.x + w2 * f1.w + w3 * f2.z;
    float img2 = w0 * f0.z + w1 * f1.y + w2 * f2.x + w3 * f2.w;

    // ---- contraction + packed xyz stores (3x STG.128) ----
    float c0x, c0y, c0z, c1x, c1y, c1z, c2x, c2y, c2z, c3x, c3y, c3z;
    contract_pt(zm0, ox, oy, oz, dx, dy, dz, c0x, c0y, c0z);
    contract_pt(zm1, ox, oy, oz, dx, dy, dz, c1x, c1y, c1z);
    contract_pt(zm2, ox, oy, oz, dx, dy, dz, c2x, c2y, c2z);
    contract_pt(zm3, ox, oy, oz, dx, dy, dz, c3x, c3y, c3z);

    const size_t base = (size_t)ray * OUTW;
    float4* xo4 = reinterpret_cast<float4*>(out + base + 4) + 3 * lane;
    xo4[0] = make_float4(c0x, c0y, c0z, c1x);
    xo4[1] = make_float4(c1y, c1z, c2x, c2y);
    xo4[2] = make_float4(c2z, c3x, c3y, c3z);

    // ---- warp reduction for image + depth (shuffle tree) ----
    #pragma unroll
    for (int o = 16; o > 0; o >>= 1) {
        img0 += __shfl_down_sync(FULL, img0, o);
        img1 += __shfl_down_sync(FULL, img1, o);
        img2 += __shfl_down_sync(FULL, img2, o);
        dep  += __shfl_down_sync(FULL, dep,  o);
    }
    if (lane == 0) {
        float4 head = make_float4(img0, img1, img2, dep);
        *reinterpret_cast<float4*>(out + base) = head;
    }
}

extern "C" void kernel_launch(void* const* d_in, const int* in_sizes, int n_in,
                              void* d_out, int out_size)
{
    const float* rays_o = (const float*)d_in[0];
    const float* rays_d = (const float*)d_in[1];
    const float* aabb   = (const float*)d_in[2];
    const float* wc     = (const float*)d_in[3];
    const float* sigmas = (const float*)d_in[4];
    const float* rgbs   = (const float*)d_in[5];
    float* out = (float*)d_out;

    const int N = in_sizes[0] / 3;   // rays_o has N*3 elements
    const int blocks = (N + WPB - 1) / WPB;
    nerf_render_kernel<<<blocks, WPB * 32>>>(
        rays_o, rays_d, aabb, wc, sigmas, rgbs, out, N);
}

// round 12
// speedup vs baseline: 1.0088x; 1.0088x over previous
#include <cuda_runtime.h>

// NeRF fused render: near/far -> coarse bins -> scatter inverse-CDF sampling ->
// contraction -> alpha compositing.
// One warp per ray. Blocked sample ownership (lane owns samples 4l..4l+3).
// Compositing via exp-difference (one additive warp scan). CDF intervals
// pair-owned per lane. rcp.approx divisions. Streaming cache hints
// (__ldcs/__stcs) on all touch-once data. Transposed final reduction.
// NOTE (measured): redux.sync is INT-ONLY on sm_103a; L2 prefetch is neutral.

constexpr int T0 = 64;     // coarse intervals
constexpr int TF = 128;    // fine samples
constexpr int OUTW = 4 + 3 * TF;     // 388 floats per ray
constexpr int WPB = 8;               // warps per block
constexpr unsigned FULL = 0xffffffffu;

__device__ __forceinline__ float frcp(float x) {
    float r;
    asm("rcp.approx.f32 %0, %1;" : "=f"(r) : "f"(x));
    return r;
}

__device__ __forceinline__ void contract_pt(float zm,
                                            float ox, float oy, float oz,
                                            float dx, float dy, float dz,
                                            float& cx, float& cy, float& cz)
{
    float x = fmaf(dx, zm, ox);
    float y = fmaf(dy, zm, oy);
    float z = fmaf(dz, zm, oz);
    const float ax = fabsf(x), ay = fabsf(y), az = fabsf(z);
    const float mag = fmaxf(ax, fmaxf(ay, az));
    cx = x; cy = y; cz = z;
    if (mag >= 1.0f) {
        const float im = frcp(mag);
        const float sm = (2.0f - im) * im;
        cx = x * im; cy = y * im; cz = z * im;
        if (ax == mag)      cx = x * sm;   // argmax tie-break order x,y,z
        else if (ay == mag) cy = y * sm;
        else                cz = z * sm;
    }
}

__global__ __launch_bounds__(WPB * 32, 8)
void nerf_render_kernel(const float* __restrict__ rays_o,
                        const float* __restrict__ rays_d,
                        const float* __restrict__ aabb,
                        const float* __restrict__ wc,     // [N, 64]
                        const float* __restrict__ sigmas, // [N, 128]
                        const float* __restrict__ rgbs,   // [N, 128, 3]
                        float* __restrict__ out,          // [N, 388]
                        int N)
{
    __shared__ __align__(16) float s_zed[WPB][TF + 8];   // 129 fine edges (+pad)

    const int warp = threadIdx.x >> 5;
    const int lane = threadIdx.x & 31;
    const int ray  = blockIdx.x * WPB + warp;
    if (ray >= N) return;

    // ---- ray + aabb ----
    const float ox = rays_o[3 * ray + 0];
    const float oy = rays_o[3 * ray + 1];
    const float oz = rays_o[3 * ray + 2];
    const float dx = rays_d[3 * ray + 0];
    const float dy = rays_d[3 * ray + 1];
    const float dz = rays_d[3 * ray + 2];

    const float ix = frcp(dx + 1e-15f);
    const float iy = frcp(dy + 1e-15f);
    const float iz = frcp(dz + 1e-15f);
    const float t0x = (aabb[0] - ox) * ix, t1x = (aabb[3] - ox) * ix;
    const float t0y = (aabb[1] - oy) * iy, t1y = (aabb[4] - oy) * iy;
    const float t0z = (aabb[2] - oz) * iz, t1z = (aabb[5] - oz) * iz;

    float nearv = fmaxf(fmaxf(fminf(t0x, t1x), fminf(t0y, t1y)), fminf(t0z, t1z));
    float farv  = fminf(fminf(fmaxf(t0x, t1x), fmaxf(t0y, t1y)), fmaxf(t0z, t1z));
    if (farv < nearv) { nearv = 1e9f; farv = 1e9f; }
    nearv = fmaxf(nearv, 0.05f);
    const float span = farv - nearv;
    const float db = span * (1.0f / 64.0f);   // coarse bin width (constant)

    // ---- CDF: lane owns weights {2l, 2l+1} -> intervals 2l, 2l+1 local ----
    const float2 wpair = __ldcs(reinterpret_cast<const float2*>(
        wc + (size_t)ray * T0 + 2 * lane));
    const float wa = wpair.x + 0.01f;
    const float wb = wpair.y + 0.01f;
    const float pair = wa + wb;

    float incl = pair;
    #pragma unroll
    for (int o = 1; o < 32; o <<= 1) {
        float v = __shfl_up_sync(FULL, incl, o);
        if (lane >= o) incl += v;
    }
    float excl = __shfl_up_sync(FULL, incl, 1);
    if (lane == 0) excl = 0.0f;
    const float inv_tot = frcp(__shfl_sync(FULL, incl, 31));

    const float c_base = fminf(excl * inv_tot, 1.0f);          // C[2l]
    const float c_mid  = fminf((excl + wa) * inv_tot, 1.0f);   // C[2l+1]
    const float c_end  = fminf(incl * inv_tot, 1.0f);          // C[2l+2]

    float* zed = s_zed[warp];

    // ---- scatter fine edges: interval k covers u in [C[k], C[k+1]) ----
    constexpr float inv129 = 1.0f / 129.0f;
    #pragma unroll
    for (int h = 0; h < 2; ++h) {
        const int k = 2 * lane + h;
        const float c0 = (h == 0) ? c_base : c_mid;
        const float c1 = (h == 0) ? c_mid : c_end;

        int j0 = (int)ceilf(fmaf(129.0f, c0, -0.5f));
        int j1 = (k == 63) ? 129 : (int)ceilf(fmaf(129.0f, c1, -0.5f));
        j0 = max(j0, 0);
        j1 = min(j1, 129);

        const float inv_den = frcp(fmaxf(c1 - c0, 1e-12f));
        const float b0 = fmaf(db, (float)k, nearv);
        const float step_t = inv_den * inv129;
        // t at j0, then stepped linearly
        float t = (fmaf((float)j0 + 0.5f, inv129, -c0)) * inv_den;

        for (int j = j0; j < j1; ++j) {
            const float tc = fminf(fmaxf(t, 0.0f), 1.0f);
            zed[j] = fmaf(tc, db, b0);
            t += step_t;
        }
    }
    __syncwarp();

    // ---- blocked compositing: lane owns samples 4l..4l+3 ----
    const float4 z4 = *reinterpret_cast<const float4*>(&zed[4 * lane]);
    const float ztop = zed[TF];                         // zed[128], broadcast
    const float znxt = __shfl_down_sync(FULL, z4.x, 1); // next lane's first edge
    const float e4 = (lane == 31) ? ztop : znxt;

    const float4 sg4 = __ldcs(reinterpret_cast<const float4*>(
        sigmas + (size_t)ray * TF + 4 * lane));

    const float q0 = sg4.x * (z4.y - z4.x);
    const float q1 = sg4.y * (z4.z - z4.y);
    const float q2 = sg4.z * (z4.w - z4.z);
    const float q3 = sg4.w * (e4   - z4.w);

    const float p1 = q0;
    const float p2 = q0 + q1;
    const float p3 = p2 + q2;
    const float Tl = p3 + q3;               // lane-local optical depth

    // single additive warp scan over lane totals
    float iS = Tl;
    #pragma unroll
    for (int o = 1; o < 32; o <<= 1) {
        float v = __shfl_up_sync(FULL, iS, o);
        if (lane >= o) iS += v;
    }
    float S0 = __shfl_up_sync(FULL, iS, 1);
    if (lane == 0) S0 = 0.0f;

    const float E0 = __expf(-S0);
    const float E1 = __expf(-(S0 + p1));
    const float E2 = __expf(-(S0 + p2));
    const float E3 = __expf(-(S0 + p3));
    const float E4 = __expf(-(S0 + Tl));

    const float w0 = E0 - E1;
    const float w1 = E1 - E2;
    const float w2 = E2 - E3;
    const float w3 = E3 - E4;

    const float zm0 = 0.5f * (z4.x + z4.y);
    const float zm1 = 0.5f * (z4.y + z4.z);
    const float zm2 = 0.5f * (z4.z + z4.w);
    const float zm3 = 0.5f * (z4.w + e4);

    float dep = w0 * zm0 + w1 * zm1 + w2 * zm2 + w3 * zm3;

    // ---- rgb: 3x LDG.128 streaming, compile-time channel mapping ----
    const float4* rg4 = reinterpret_cast<const float4*>(
        rgbs + (size_t)ray * TF * 3) + 3 * lane;
    const float4 f0 = __ldcs(rg4 + 0);
    const float4 f1 = __ldcs(rg4 + 1);
    const float4 f2 = __ldcs(rg4 + 2);

    float img0 = w0 * f0.x + w1 * f0.w + w2 * f1.z + w3 * f2.y;
    float img1 = w0 * f0.y + w1 * f1.x + w2 * f1.w + w3 * f2.z;
    float img2 = w0 * f0.z + w1 * f1.y + w2 * f2.x + w3 * f2.w;

    // ---- contraction + packed xyz streaming stores (3x STG.128) ----
    float c0x, c0y, c0z, c1x, c1y, c1z, c2x, c2y, c2z, c3x, c3y, c3z;
    contract_pt(zm0, ox, oy, oz, dx, dy, dz, c0x, c0y, c0z);
    contract_pt(zm1, ox, oy, oz, dx, dy, dz, c1x, c1y, c1z);
    contract_pt(zm2, ox, oy, oz, dx, dy, dz, c2x, c2y, c2z);
    contract_pt(zm3, ox, oy, oz, dx, dy, dz, c3x, c3y, c3z);

    const size_t base = (size_t)ray * OUTW;
    float4* xo4 = reinterpret_cast<float4*>(out + base + 4) + 3 * lane;
    __stcs(xo4 + 0, make_float4(c0x, c0y, c0z, c1x));
    __stcs(xo4 + 1, make_float4(c1y, c1z, c2x, c2y));
    __stcs(xo4 + 2, make_float4(c2z, c3x, c3y, c3z));

    // ---- transposed warp reduction: 15 SHFL instead of 20 ----
    #pragma unroll
    for (int o = 16; o >= 8; o >>= 1) {
        img0 += __shfl_down_sync(FULL, img0, o);
        img1 += __shfl_down_sync(FULL, img1, o);
        img2 += __shfl_down_sync(FULL, img2, o);
        dep  += __shfl_down_sync(FULL, dep,  o);
    }
    // partials now in lanes 0..7; lane l fetches quantity (l>>3) from lane (l&7)
    const int src = lane & 7;
    const float a0 = __shfl_sync(FULL, img0, src);
    const float a1 = __shfl_sync(FULL, img1, src);
    const float a2 = __shfl_sync(FULL, img2, src);
    const float a3 = __shfl_sync(FULL, dep,  src);
    const int q = lane >> 3;
    float m = (q == 0) ? a0 : (q == 1) ? a1 : (q == 2) ? a2 : a3;
    #pragma unroll
    for (int o = 4; o > 0; o >>= 1)
        m += __shfl_down_sync(FULL, m, o);
    if (src == 0)
        __stcs(out + base + q, m);   // 4 lanes, one 16B segment
}

extern "C" void kernel_launch(void* const* d_in, const int* in_sizes, int n_in,
                              void* d_out, int out_size)
{
    const float* rays_o = (const float*)d_in[0];
    const float* rays_d = (const float*)d_in[1];
    const float* aabb   = (const float*)d_in[2];
    const float* wc     = (const float*)d_in[3];
    const float* sigmas = (const float*)d_in[4];
    const float* rgbs   = (const float*)d_in[5];
    float* out = (float*)d_out;

    const int N = in_sizes[0] / 3;   // rays_o has N*3 elements
    const int blocks = (N + WPB - 1) / WPB;
    nerf_render_kernel<<<blocks, WPB * 32>>>(
        rays_o, rays_d, aabb, wc, sigmas, rgbs, out, N);
}